// round 16
// baseline (speedup 1.0000x reference)
#include <cuda_runtime.h>
#include <cuda_fp16.h>
#include <cstdint>

#define N_NODES 100000
#define N_EDGES 1600000
#define DIM     128
#define SCAN_BS 1024
#define NSCAN   ((N_NODES + SCAN_BS - 1) / SCAN_BS)   // 98

#define SCAT_BLOCKS ((N_EDGES + 255) / 256)            // 6250
#define CVT_BLOCKS  ((N_NODES * DIM / 8 + 255) / 256)  // 6250

// Scratch (no cudaMalloc allowed)
__device__ __half   g_agg16[(size_t)N_NODES * DIM];  // fp16 normalized aggregate
__device__ __half   g_h16[(size_t)N_NODES * DIM];    // fp16 h prescaled by norm[row]
__device__ int      g_deg[N_NODES];
__device__ float    g_norm[N_NODES];
__device__ unsigned g_scan_pack[NSCAN];              // (status<<30)|agg-or-prefix
__device__ int      g_row_start[N_NODES + 1];
__device__ int      g_cursor[N_NODES];
__device__ int      g_sorted_src[N_EDGES];

// ---------------------------------------------------------------------------
// 1. zero degree counters + scan flags
// ---------------------------------------------------------------------------
__global__ void zero_deg_kernel() {
    int i = blockIdx.x * blockDim.x + threadIdx.x;
    if (i < N_NODES) g_deg[i] = 0;
    if (i < NSCAN)  g_scan_pack[i] = 0u;
}

// ---------------------------------------------------------------------------
// 2. in-degree histogram (1 edge/thread: max atomic MLP)
// ---------------------------------------------------------------------------
__global__ void deg_kernel(const int* __restrict__ edge_dst) {
    int i = blockIdx.x * blockDim.x + threadIdx.x;
    if (i < N_EDGES) atomicAdd(&g_deg[edge_dst[i]], 1);
}

// ---------------------------------------------------------------------------
// 3. single-pass decoupled-lookback scan + finalize
// ---------------------------------------------------------------------------
#define ST_AGG  (1u << 30)
#define ST_PREF (2u << 30)
#define VAL_MASK ((1u << 30) - 1u)

__global__ __launch_bounds__(SCAN_BS)
void scan_finalize_kernel() {
    __shared__ int s[SCAN_BS];
    __shared__ int s_prefix;
    int tid = threadIdx.x;
    int b   = blockIdx.x;
    int gi  = b * SCAN_BS + tid;

    int v = (gi < N_NODES) ? g_deg[gi] : 0;
    s[tid] = v;
    __syncthreads();
#pragma unroll
    for (int off = 1; off < SCAN_BS; off <<= 1) {
        int t = (tid >= off) ? s[tid - off] : 0;
        __syncthreads();
        s[tid] += t;
        __syncthreads();
    }
    int incl = s[tid];                  // inclusive local scan
    int aggregate = s[SCAN_BS - 1];

    if (tid == 0) {
        if (b == 0) {
            atomicExch(&g_scan_pack[0], ST_PREF | (unsigned)aggregate);
            s_prefix = 0;
        } else {
            atomicExch(&g_scan_pack[b], ST_AGG | (unsigned)aggregate);
            int sum = 0;
            int j = b - 1;
            while (true) {
                unsigned p = atomicAdd(&g_scan_pack[j], 0u);
                unsigned st = p & ~VAL_MASK;
                if (st == 0u) continue;          // not published yet
                sum += (int)(p & VAL_MASK);
                if (st == ST_PREF) break;
                j--;
            }
            s_prefix = sum;
            atomicExch(&g_scan_pack[b], ST_PREF | (unsigned)(sum + aggregate));
        }
    }
    __syncthreads();

    if (gi < N_NODES) {
        int rs = s_prefix + incl - v;   // exclusive global prefix
        g_row_start[gi] = rs;
        g_cursor[gi]    = rs;
        g_norm[gi] = rsqrtf((float)(v > 0 ? v : 1));
    }
    if (gi == N_NODES - 1) g_row_start[N_NODES] = N_EDGES;
}

// ---------------------------------------------------------------------------
// 4. FUSED: edge bucketing (1 edge/thread) + h -> prescaled fp16 conversion
// ---------------------------------------------------------------------------
__global__ __launch_bounds__(256)
void scatter_cvt_kernel(const float* __restrict__ h,
                        const int*   __restrict__ edge_src,
                        const int*   __restrict__ edge_dst) {
    int b = blockIdx.x;
    if (b < SCAT_BLOCKS) {
        int e = b * 256 + threadIdx.x;
        if (e < N_EDGES) {
            int d = edge_dst[e];
            int pos = atomicAdd(&g_cursor[d], 1);
            g_sorted_src[pos] = edge_src[e];
        }
    } else {
        int i = (b - SCAT_BLOCKS) * 256 + threadIdx.x;   // over N*DIM/8
        if (i < N_NODES * DIM / 8) {
            float nr = __ldg(&g_norm[i >> 4]);
            const float4* h4 = (const float4*)h;
            float4 a = __ldg(&h4[i * 2]);
            float4 bb = __ldg(&h4[i * 2 + 1]);
            __half2 p0 = __floats2half2_rn(a.x * nr, a.y * nr);
            __half2 p1 = __floats2half2_rn(a.z * nr, a.w * nr);
            __half2 p2 = __floats2half2_rn(bb.x * nr, bb.y * nr);
            __half2 p3 = __floats2half2_rn(bb.z * nr, bb.w * nr);
            uint4 o;
            o.x = *(uint32_t*)&p0; o.y = *(uint32_t*)&p1;
            o.z = *(uint32_t*)&p2; o.w = *(uint32_t*)&p3;
            ((uint4*)g_h16)[i] = o;
        }
    }
}

// ---------------------------------------------------------------------------
// 5. gather-aggregate (R13-proven): one warp per node, fp32 acc, fp16 store.
//    Unroll 8 + tail 4 + singles.
// ---------------------------------------------------------------------------
__global__ __launch_bounds__(256)
void gather_kernel() {
    int warp = (blockIdx.x * blockDim.x + threadIdx.x) >> 5;
    int lane = threadIdx.x & 31;
    if (warp >= N_NODES) return;

    int start = __ldg(&g_row_start[warp]);
    int end   = __ldg(&g_row_start[warp + 1]);

    const uint2* h2 = (const uint2*)g_h16;   // 32 uint2 per row
    float4 acc = make_float4(0.f, 0.f, 0.f, 0.f);

    int e = start;
    for (; e + 7 < end; e += 8) {
        int s[8];
#pragma unroll
        for (int j = 0; j < 8; j++) s[j] = __ldg(&g_sorted_src[e + j]);
        uint2 u[8];
#pragma unroll
        for (int j = 0; j < 8; j++) u[j] = __ldg(&h2[(size_t)s[j] * 32 + lane]);
#pragma unroll
        for (int j = 0; j < 8; j++) {
            float2 a = __half22float2(*(__half2*)&u[j].x);
            float2 b = __half22float2(*(__half2*)&u[j].y);
            acc.x += a.x; acc.y += a.y;
            acc.z += b.x; acc.w += b.y;
        }
    }
    if (e + 3 < end) {
        int s[4];
#pragma unroll
        for (int j = 0; j < 4; j++) s[j] = __ldg(&g_sorted_src[e + j]);
        uint2 u[4];
#pragma unroll
        for (int j = 0; j < 4; j++) u[j] = __ldg(&h2[(size_t)s[j] * 32 + lane]);
#pragma unroll
        for (int j = 0; j < 4; j++) {
            float2 a = __half22float2(*(__half2*)&u[j].x);
            float2 b = __half22float2(*(__half2*)&u[j].y);
            acc.x += a.x; acc.y += a.y;
            acc.z += b.x; acc.w += b.y;
        }
        e += 4;
    }
    for (; e < end; e++) {
        int s0 = __ldg(&g_sorted_src[e]);
        uint2 u0 = __ldg(&h2[(size_t)s0 * 32 + lane]);
        float2 a0 = __half22float2(*(__half2*)&u0.x);
        float2 b0 = __half22float2(*(__half2*)&u0.y);
        acc.x += a0.x; acc.y += a0.y;
        acc.z += b0.x; acc.w += b0.y;
    }

    float nd = __ldg(&g_norm[warp]);
    __half2 p0 = __floats2half2_rn(acc.x * nd, acc.y * nd);
    __half2 p1 = __floats2half2_rn(acc.z * nd, acc.w * nd);
    uint2 o;
    o.x = *(uint32_t*)&p0;
    o.y = *(uint32_t*)&p1;
    ((uint2*)g_agg16)[(size_t)warp * 32 + lane] = o;
}

// ---------------------------------------------------------------------------
// 6. fp16 ldmatrix MMA GEMM: out = aggn @ W^T + b
//    m16n8k16, fp32 acc. 8 warps: 4m x 2n, warp tile 32x64.
// ---------------------------------------------------------------------------
#define SH_STRIDE 136
#define SMEM_HALF_W (128 * SH_STRIDE)                 // halves
#define SMEM_SZ (2 * SMEM_HALF_W * 2)                 // 69632 B

#define LDSM_X4(r0, r1, r2, r3, addr) \
    asm volatile("ldmatrix.sync.aligned.m8n8.x4.shared.b16 {%0,%1,%2,%3}, [%4];" \
        : "=r"(r0), "=r"(r1), "=r"(r2), "=r"(r3) : "r"(addr))

__global__ __launch_bounds__(256)
void mma_gemm_kernel(const float* __restrict__ W,
                     const float* __restrict__ bias,
                     float*       __restrict__ out) {
    extern __shared__ __half smh[];
    __half* sW = smh;                    // [n][k]
    __half* sA = smh + SMEM_HALF_W;      // [m][k]

    int tid  = threadIdx.x;
    int lane = tid & 31;
    int warp = tid >> 5;
    int wm   = warp & 3;      // m0 = wm*32
    int wn   = warp >> 2;     // n0 = wn*64
    int row0 = blockIdx.x * 128;

    // ---- stage W as fp16 ----
    {
        const float4* W4 = (const float4*)W;
#pragma unroll
        for (int t = tid; t < 4096; t += 256) {
            int n = t >> 5;
            int q = t & 31;
            float4 w = __ldg(&W4[n * 32 + q]);
            __half2 h0 = __floats2half2_rn(w.x, w.y);
            __half2 h1 = __floats2half2_rn(w.z, w.w);
            uint32_t* p = (uint32_t*)&sW[n * SH_STRIDE + q * 4];
            p[0] = *(uint32_t*)&h0;
            p[1] = *(uint32_t*)&h1;
        }
    }
    // ---- stage A (fp16 bit-copy) ----
    {
        const uint2* A2 = (const uint2*)g_agg16;
#pragma unroll
        for (int t = tid; t < 4096; t += 256) {
            int m = t >> 5;
            int q = t & 31;
            int row = row0 + m;
            uint2 a = make_uint2(0u, 0u);
            if (row < N_NODES) a = __ldg(&A2[(size_t)row * 32 + q]);
            uint32_t* p = (uint32_t*)&sA[m * SH_STRIDE + q * 4];
            p[0] = a.x;
            p[1] = a.y;
        }
    }
    __syncthreads();

    float acc[2][8][4];
#pragma unroll
    for (int mt = 0; mt < 2; mt++)
#pragma unroll
        for (int nt = 0; nt < 8; nt++)
#pragma unroll
            for (int c = 0; c < 4; c++) acc[mt][nt][c] = 0.f;

    uint32_t sA_base = (uint32_t)__cvta_generic_to_shared(sA);
    uint32_t sW_base = (uint32_t)__cvta_generic_to_shared(sW);

#pragma unroll
    for (int ks = 0; ks < 8; ks++) {
        int k0 = ks * 16;
        uint32_t a[2][4];
#pragma unroll
        for (int mt = 0; mt < 2; mt++) {
            int r = wm * 32 + mt * 16 + (lane & 15);
            int c = k0 + ((lane >> 4) << 3);
            uint32_t addr = sA_base + (uint32_t)(r * SH_STRIDE + c) * 2;
            LDSM_X4(a[mt][0], a[mt][1], a[mt][2], a[mt][3], addr);
        }
        uint32_t b[4][4];
#pragma unroll
        for (int p = 0; p < 4; p++) {
            int n = wn * 64 + p * 16 + ((lane >= 16) ? 8 : 0) + (lane & 7);
            int c = k0 + (((lane >> 3) & 1) << 3);
            uint32_t addr = sW_base + (uint32_t)(n * SH_STRIDE + c) * 2;
            LDSM_X4(b[p][0], b[p][1], b[p][2], b[p][3], addr);
        }
#pragma unroll
        for (int nt = 0; nt < 8; nt++) {
            uint32_t b0 = b[nt >> 1][(nt & 1) ? 2 : 0];
            uint32_t b1 = b[nt >> 1][(nt & 1) ? 3 : 1];
#pragma unroll
            for (int mt = 0; mt < 2; mt++) {
                asm volatile(
                    "mma.sync.aligned.m16n8k16.row.col.f32.f16.f16.f32 "
                    "{%0,%1,%2,%3}, {%4,%5,%6,%7}, {%8,%9}, {%0,%1,%2,%3};"
                    : "+f"(acc[mt][nt][0]), "+f"(acc[mt][nt][1]),
                      "+f"(acc[mt][nt][2]), "+f"(acc[mt][nt][3])
                    : "r"(a[mt][0]), "r"(a[mt][1]),
                      "r"(a[mt][2]), "r"(a[mt][3]),
                      "r"(b0), "r"(b1));
            }
        }
    }

    // ---- epilogue: bias + store ----
#pragma unroll
    for (int mt = 0; mt < 2; mt++) {
        int r0 = row0 + wm * 32 + mt * 16 + (lane >> 2);
        int r1 = r0 + 8;
#pragma unroll
        for (int nt = 0; nt < 8; nt++) {
            int c = wn * 64 + nt * 8 + (lane & 3) * 2;
            float2 bb = __ldg((const float2*)&bias[c]);
            if (r0 < N_NODES) {
                float2 o = make_float2(acc[mt][nt][0] + bb.x,
                                       acc[mt][nt][1] + bb.y);
                *(float2*)&out[(size_t)r0 * DIM + c] = o;
            }
            if (r1 < N_NODES) {
                float2 o = make_float2(acc[mt][nt][2] + bb.x,
                                       acc[mt][nt][3] + bb.y);
                *(float2*)&out[(size_t)r1 * DIM + c] = o;
            }
        }
    }
}

// ---------------------------------------------------------------------------
// Launch
// ---------------------------------------------------------------------------
extern "C" void kernel_launch(void* const* d_in, const int* in_sizes, int n_in,
                              void* d_out, int out_size) {
    const float* h        = (const float*)d_in[0];
    const float* W        = (const float*)d_in[1];
    const float* b        = (const float*)d_in[2];
    const int*   edge_src = (const int*)d_in[3];
    const int*   edge_dst = (const int*)d_in[4];
    float*       out      = (float*)d_out;

    zero_deg_kernel<<<(N_NODES + 255) / 256, 256>>>();
    deg_kernel<<<(N_EDGES + 255) / 256, 256>>>(edge_dst);
    scan_finalize_kernel<<<NSCAN, SCAN_BS>>>();
    scatter_cvt_kernel<<<SCAT_BLOCKS + CVT_BLOCKS, 256>>>(h, edge_src, edge_dst);

    {   // one warp per node
        int blocks = (N_NODES + 7) / 8;
        gather_kernel<<<blocks, 256>>>();
    }

    (void)cudaFuncSetAttribute(mma_gemm_kernel,
                               cudaFuncAttributeMaxDynamicSharedMemorySize,
                               SMEM_SZ);
    int tiles = (N_NODES + 127) / 128;   // 782
    mma_gemm_kernel<<<tiles, 256, SMEM_SZ>>>(W, b, out);
}

// round 17
// speedup vs baseline: 1.0351x; 1.0351x over previous
#include <cuda_runtime.h>
#include <cuda_fp16.h>
#include <cstdint>

#define N_NODES 100000
#define N_EDGES 1600000
#define DIM     128
#define SCAN_BS 1024
#define NSCAN   ((N_NODES + SCAN_BS - 1) / SCAN_BS)   // 98

#define SCAT_BLOCKS ((N_EDGES + 255) / 256)            // 6250
#define CVT_BLOCKS  ((N_NODES * DIM / 8 + 255) / 256)  // 6250

// Scratch (no cudaMalloc allowed)
__device__ __half   g_agg16[(size_t)N_NODES * DIM];  // fp16 normalized aggregate
__device__ __half   g_h16[(size_t)N_NODES * DIM];    // fp16 h prescaled by norm[row]
__device__ int      g_deg[N_NODES];
__device__ float    g_norm[N_NODES];
__device__ unsigned g_scan_pack[NSCAN];              // (status<<30)|agg-or-prefix
__device__ int      g_row_start[N_NODES + 1];
__device__ int      g_cursor[N_NODES];
__device__ int      g_sorted_src[N_EDGES];

// ---------------------------------------------------------------------------
// 1. zero degree counters + scan flags
// ---------------------------------------------------------------------------
__global__ void zero_deg_kernel() {
    int i = blockIdx.x * blockDim.x + threadIdx.x;
    if (i < N_NODES) g_deg[i] = 0;
    if (i < NSCAN)  g_scan_pack[i] = 0u;
}

// ---------------------------------------------------------------------------
// 2. in-degree histogram (1 edge/thread: max atomic MLP)
// ---------------------------------------------------------------------------
__global__ void deg_kernel(const int* __restrict__ edge_dst) {
    int i = blockIdx.x * blockDim.x + threadIdx.x;
    if (i < N_EDGES) atomicAdd(&g_deg[edge_dst[i]], 1);
}

// ---------------------------------------------------------------------------
// 3. single-pass scan + finalize, WARP-PARALLEL decoupled lookback.
//    Local scan: shfl-based two-level (2 barriers).
//    Lookback: warp 0 reads 32 predecessor flags per round.
// ---------------------------------------------------------------------------
#define ST_AGG  (1u << 30)
#define ST_PREF (2u << 30)
#define VAL_MASK ((1u << 30) - 1u)

__global__ __launch_bounds__(SCAN_BS)
void scan_finalize_kernel() {
    __shared__ int s_wsum[32];
    __shared__ int s_prefix;
    int tid  = threadIdx.x;
    int lane = tid & 31;
    int wid  = tid >> 5;
    int b    = blockIdx.x;
    int gi   = b * SCAN_BS + tid;

    int v = (gi < N_NODES) ? g_deg[gi] : 0;

    // warp-level inclusive scan
    int x = v;
#pragma unroll
    for (int o = 1; o < 32; o <<= 1) {
        int t = __shfl_up_sync(0xFFFFFFFFu, x, o);
        if (lane >= o) x += t;
    }
    if (lane == 31) s_wsum[wid] = x;
    __syncthreads();
    if (wid == 0) {
        int w = s_wsum[lane];
#pragma unroll
        for (int o = 1; o < 32; o <<= 1) {
            int t = __shfl_up_sync(0xFFFFFFFFu, w, o);
            if (lane >= o) w += t;
        }
        s_wsum[lane] = w;          // inclusive warp sums
    }
    __syncthreads();
    int warp_excl = (wid == 0) ? 0 : s_wsum[wid - 1];
    int incl      = x + warp_excl;        // block-inclusive scan of v
    int aggregate = s_wsum[31];

    // decoupled lookback (warp 0, 32-wide window)
    if (wid == 0) {
        if (b == 0) {
            if (lane == 0) {
                atomicExch(&g_scan_pack[0], ST_PREF | (unsigned)aggregate);
                s_prefix = 0;
            }
        } else {
            if (lane == 0)
                atomicExch(&g_scan_pack[b], ST_AGG | (unsigned)aggregate);
            __syncwarp();
            int sum = 0;
            int j = b - 1;
            while (true) {
                int idx = j - lane;
                unsigned p = (idx >= 0) ? atomicAdd(&g_scan_pack[idx], 0u)
                                        : ST_PREF;       // virtual prefix 0
                unsigned st = p & ~VAL_MASK;
                if (__ballot_sync(0xFFFFFFFFu, st == 0u)) continue;  // retry
                unsigned prefmask = __ballot_sync(0xFFFFFFFFu, st == ST_PREF);
                if (prefmask) {
                    int fp = __ffs(prefmask) - 1;        // nearest PREF
                    int c = (lane <= fp) ? (int)(p & VAL_MASK) : 0;
#pragma unroll
                    for (int o = 16; o; o >>= 1)
                        c += __shfl_xor_sync(0xFFFFFFFFu, c, o);
                    sum += c;
                    break;
                } else {
                    int c = (int)(p & VAL_MASK);
#pragma unroll
                    for (int o = 16; o; o >>= 1)
                        c += __shfl_xor_sync(0xFFFFFFFFu, c, o);
                    sum += c;
                    j -= 32;
                }
            }
            if (lane == 0) {
                s_prefix = sum;
                atomicExch(&g_scan_pack[b], ST_PREF | (unsigned)(sum + aggregate));
            }
        }
    }
    __syncthreads();

    if (gi < N_NODES) {
        int rs = s_prefix + incl - v;     // exclusive global prefix
        g_row_start[gi] = rs;
        g_cursor[gi]    = rs;
        g_norm[gi] = rsqrtf((float)(v > 0 ? v : 1));
    }
    if (gi == N_NODES - 1) g_row_start[N_NODES] = N_EDGES;
}

// ---------------------------------------------------------------------------
// 4. FUSED: edge bucketing (1 edge/thread) + h -> prescaled fp16 conversion
// ---------------------------------------------------------------------------
__global__ __launch_bounds__(256)
void scatter_cvt_kernel(const float* __restrict__ h,
                        const int*   __restrict__ edge_src,
                        const int*   __restrict__ edge_dst) {
    int b = blockIdx.x;
    if (b < SCAT_BLOCKS) {
        int e = b * 256 + threadIdx.x;
        if (e < N_EDGES) {
            int d = edge_dst[e];
            int pos = atomicAdd(&g_cursor[d], 1);
            g_sorted_src[pos] = edge_src[e];
        }
    } else {
        int i = (b - SCAT_BLOCKS) * 256 + threadIdx.x;   // over N*DIM/8
        if (i < N_NODES * DIM / 8) {
            float nr = __ldg(&g_norm[i >> 4]);
            const float4* h4 = (const float4*)h;
            float4 a = __ldg(&h4[i * 2]);
            float4 bb = __ldg(&h4[i * 2 + 1]);
            __half2 p0 = __floats2half2_rn(a.x * nr, a.y * nr);
            __half2 p1 = __floats2half2_rn(a.z * nr, a.w * nr);
            __half2 p2 = __floats2half2_rn(bb.x * nr, bb.y * nr);
            __half2 p3 = __floats2half2_rn(bb.z * nr, bb.w * nr);
            uint4 o;
            o.x = *(uint32_t*)&p0; o.y = *(uint32_t*)&p1;
            o.z = *(uint32_t*)&p2; o.w = *(uint32_t*)&p3;
            ((uint4*)g_h16)[i] = o;
        }
    }
}

// ---------------------------------------------------------------------------
// 5. gather-aggregate (R13-proven): one warp per node, fp32 acc, fp16 store.
// ---------------------------------------------------------------------------
__global__ __launch_bounds__(256)
void gather_kernel() {
    int warp = (blockIdx.x * blockDim.x + threadIdx.x) >> 5;
    int lane = threadIdx.x & 31;
    if (warp >= N_NODES) return;

    int start = __ldg(&g_row_start[warp]);
    int end   = __ldg(&g_row_start[warp + 1]);

    const uint2* h2 = (const uint2*)g_h16;   // 32 uint2 per row
    float4 acc = make_float4(0.f, 0.f, 0.f, 0.f);

    int e = start;
    for (; e + 7 < end; e += 8) {
        int s[8];
#pragma unroll
        for (int j = 0; j < 8; j++) s[j] = __ldg(&g_sorted_src[e + j]);
        uint2 u[8];
#pragma unroll
        for (int j = 0; j < 8; j++) u[j] = __ldg(&h2[(size_t)s[j] * 32 + lane]);
#pragma unroll
        for (int j = 0; j < 8; j++) {
            float2 a = __half22float2(*(__half2*)&u[j].x);
            float2 b = __half22float2(*(__half2*)&u[j].y);
            acc.x += a.x; acc.y += a.y;
            acc.z += b.x; acc.w += b.y;
        }
    }
    if (e + 3 < end) {
        int s[4];
#pragma unroll
        for (int j = 0; j < 4; j++) s[j] = __ldg(&g_sorted_src[e + j]);
        uint2 u[4];
#pragma unroll
        for (int j = 0; j < 4; j++) u[j] = __ldg(&h2[(size_t)s[j] * 32 + lane]);
#pragma unroll
        for (int j = 0; j < 4; j++) {
            float2 a = __half22float2(*(__half2*)&u[j].x);
            float2 b = __half22float2(*(__half2*)&u[j].y);
            acc.x += a.x; acc.y += a.y;
            acc.z += b.x; acc.w += b.y;
        }
        e += 4;
    }
    for (; e < end; e++) {
        int s0 = __ldg(&g_sorted_src[e]);
        uint2 u0 = __ldg(&h2[(size_t)s0 * 32 + lane]);
        float2 a0 = __half22float2(*(__half2*)&u0.x);
        float2 b0 = __half22float2(*(__half2*)&u0.y);
        acc.x += a0.x; acc.y += a0.y;
        acc.z += b0.x; acc.w += b0.y;
    }

    float nd = __ldg(&g_norm[warp]);
    __half2 p0 = __floats2half2_rn(acc.x * nd, acc.y * nd);
    __half2 p1 = __floats2half2_rn(acc.z * nd, acc.w * nd);
    uint2 o;
    o.x = *(uint32_t*)&p0;
    o.y = *(uint32_t*)&p1;
    ((uint2*)g_agg16)[(size_t)warp * 32 + lane] = o;
}

// ---------------------------------------------------------------------------
// 6. fp16 ldmatrix MMA GEMM: out = aggn @ W^T + b
// ---------------------------------------------------------------------------
#define SH_STRIDE 136
#define SMEM_HALF_W (128 * SH_STRIDE)                 // halves
#define SMEM_SZ (2 * SMEM_HALF_W * 2)                 // 69632 B

#define LDSM_X4(r0, r1, r2, r3, addr) \
    asm volatile("ldmatrix.sync.aligned.m8n8.x4.shared.b16 {%0,%1,%2,%3}, [%4];" \
        : "=r"(r0), "=r"(r1), "=r"(r2), "=r"(r3) : "r"(addr))

__global__ __launch_bounds__(256)
void mma_gemm_kernel(const float* __restrict__ W,
                     const float* __restrict__ bias,
                     float*       __restrict__ out) {
    extern __shared__ __half smh[];
    __half* sW = smh;                    // [n][k]
    __half* sA = smh + SMEM_HALF_W;      // [m][k]

    int tid  = threadIdx.x;
    int lane = tid & 31;
    int warp = tid >> 5;
    int wm   = warp & 3;      // m0 = wm*32
    int wn   = warp >> 2;     // n0 = wn*64
    int row0 = blockIdx.x * 128;

    // ---- stage W as fp16 ----
    {
        const float4* W4 = (const float4*)W;
#pragma unroll
        for (int t = tid; t < 4096; t += 256) {
            int n = t >> 5;
            int q = t & 31;
            float4 w = __ldg(&W4[n * 32 + q]);
            __half2 h0 = __floats2half2_rn(w.x, w.y);
            __half2 h1 = __floats2half2_rn(w.z, w.w);
            uint32_t* p = (uint32_t*)&sW[n * SH_STRIDE + q * 4];
            p[0] = *(uint32_t*)&h0;
            p[1] = *(uint32_t*)&h1;
        }
    }
    // ---- stage A (fp16 bit-copy) ----
    {
        const uint2* A2 = (const uint2*)g_agg16;
#pragma unroll
        for (int t = tid; t < 4096; t += 256) {
            int m = t >> 5;
            int q = t & 31;
            int row = row0 + m;
            uint2 a = make_uint2(0u, 0u);
            if (row < N_NODES) a = __ldg(&A2[(size_t)row * 32 + q]);
            uint32_t* p = (uint32_t*)&sA[m * SH_STRIDE + q * 4];
            p[0] = a.x;
            p[1] = a.y;
        }
    }
    __syncthreads();

    float acc[2][8][4];
#pragma unroll
    for (int mt = 0; mt < 2; mt++)
#pragma unroll
        for (int nt = 0; nt < 8; nt++)
#pragma unroll
            for (int c = 0; c < 4; c++) acc[mt][nt][c] = 0.f;

    uint32_t sA_base = (uint32_t)__cvta_generic_to_shared(sA);
    uint32_t sW_base = (uint32_t)__cvta_generic_to_shared(sW);

#pragma unroll
    for (int ks = 0; ks < 8; ks++) {
        int k0 = ks * 16;
        uint32_t a[2][4];
#pragma unroll
        for (int mt = 0; mt < 2; mt++) {
            int r = wm * 32 + mt * 16 + (lane & 15);
            int c = k0 + ((lane >> 4) << 3);
            uint32_t addr = sA_base + (uint32_t)(r * SH_STRIDE + c) * 2;
            LDSM_X4(a[mt][0], a[mt][1], a[mt][2], a[mt][3], addr);
        }
        uint32_t b[4][4];
#pragma unroll
        for (int p = 0; p < 4; p++) {
            int n = wn * 64 + p * 16 + ((lane >= 16) ? 8 : 0) + (lane & 7);
            int c = k0 + (((lane >> 3) & 1) << 3);
            uint32_t addr = sW_base + (uint32_t)(n * SH_STRIDE + c) * 2;
            LDSM_X4(b[p][0], b[p][1], b[p][2], b[p][3], addr);
        }
#pragma unroll
        for (int nt = 0; nt < 8; nt++) {
            uint32_t b0 = b[nt >> 1][(nt & 1) ? 2 : 0];
            uint32_t b1 = b[nt >> 1][(nt & 1) ? 3 : 1];
#pragma unroll
            for (int mt = 0; mt < 2; mt++) {
                asm volatile(
                    "mma.sync.aligned.m16n8k16.row.col.f32.f16.f16.f32 "
                    "{%0,%1,%2,%3}, {%4,%5,%6,%7}, {%8,%9}, {%0,%1,%2,%3};"
                    : "+f"(acc[mt][nt][0]), "+f"(acc[mt][nt][1]),
                      "+f"(acc[mt][nt][2]), "+f"(acc[mt][nt][3])
                    : "r"(a[mt][0]), "r"(a[mt][1]),
                      "r"(a[mt][2]), "r"(a[mt][3]),
                      "r"(b0), "r"(b1));
            }
        }
    }

    // ---- epilogue: bias + store ----
#pragma unroll
    for (int mt = 0; mt < 2; mt++) {
        int r0 = row0 + wm * 32 + mt * 16 + (lane >> 2);
        int r1 = r0 + 8;
#pragma unroll
        for (int nt = 0; nt < 8; nt++) {
            int c = wn * 64 + nt * 8 + (lane & 3) * 2;
            float2 bb = __ldg((const float2*)&bias[c]);
            if (r0 < N_NODES) {
                float2 o = make_float2(acc[mt][nt][0] + bb.x,
                                       acc[mt][nt][1] + bb.y);
                *(float2*)&out[(size_t)r0 * DIM + c] = o;
            }
            if (r1 < N_NODES) {
                float2 o = make_float2(acc[mt][nt][2] + bb.x,
                                       acc[mt][nt][3] + bb.y);
                *(float2*)&out[(size_t)r1 * DIM + c] = o;
            }
        }
    }
}

// ---------------------------------------------------------------------------
// Launch
// ---------------------------------------------------------------------------
extern "C" void kernel_launch(void* const* d_in, const int* in_sizes, int n_in,
                              void* d_out, int out_size) {
    const float* h        = (const float*)d_in[0];
    const float* W        = (const float*)d_in[1];
    const float* b        = (const float*)d_in[2];
    const int*   edge_src = (const int*)d_in[3];
    const int*   edge_dst = (const int*)d_in[4];
    float*       out      = (float*)d_out;

    zero_deg_kernel<<<(N_NODES + 255) / 256, 256>>>();
    deg_kernel<<<(N_EDGES + 255) / 256, 256>>>(edge_dst);
    scan_finalize_kernel<<<NSCAN, SCAN_BS>>>();
    scatter_cvt_kernel<<<SCAT_BLOCKS + CVT_BLOCKS, 256>>>(h, edge_src, edge_dst);

    {   // one warp per node
        int blocks = (N_NODES + 7) / 8;
        gather_kernel<<<blocks, 256>>>();
    }

    (void)cudaFuncSetAttribute(mma_gemm_kernel,
                               cudaFuncAttributeMaxDynamicSharedMemorySize,
                               SMEM_SZ);
    int tiles = (N_NODES + 127) / 128;   // 782
    mma_gemm_kernel<<<tiles, 256, SMEM_SZ>>>(W, b, out);
}